// round 17
// baseline (speedup 1.0000x reference)
#include <cuda_runtime.h>
#include <cuda_bf16.h>
#include <cstddef>

// ============================================================================
// MiniQuixerPQCBlock — exact MPS (bond dim 16), warp-register environments.
// R16: j-carry bit moved in-thread -> env = 16 lanes x 8 complex, so ONE warp
// hosts TWO chains (two batches) in its half-warps. 4 shfl passes + 3
// in-thread passes per site; packed f32x2 math; Z fused via 15-slot Hist.
// CTA = 64 threads = {L warp, R warp} for 2 batches.
// ============================================================================

typedef unsigned long long u64;

__device__ __forceinline__ u64 pk2(float lo, float hi) {
    u64 r; asm("mov.b64 %0, {%1, %2};" : "=l"(r) : "f"(lo), "f"(hi)); return r;
}
__device__ __forceinline__ u64 spl(float v) { return pk2(v, v); }
__device__ __forceinline__ float2 up2(u64 v) {
    float2 r; asm("mov.b64 {%0, %1}, %2;" : "=f"(r.x), "=f"(r.y) : "l"(v)); return r;
}
__device__ __forceinline__ u64 swp(u64 v) { float2 t = up2(v); return pk2(t.y, t.x); }
__device__ __forceinline__ u64 ffma2(u64 a, u64 b, u64 c) {
    u64 r; asm("fma.rn.f32x2 %0, %1, %2, %3;" : "=l"(r) : "l"(a), "l"(b), "l"(c)); return r;
}
__device__ __forceinline__ u64 fmul2(u64 a, u64 b) {
    u64 r; asm("mul.rn.f32x2 %0, %1, %2;" : "=l"(r) : "l"(a), "l"(b)); return r;
}
__device__ __forceinline__ u64 shfl64(u64 v, int m) { return __shfl_xor_sync(0xffffffffu, v, m); }
__device__ __forceinline__ float2 cmul(float2 a, float2 b) {
    return make_float2(fmaf(a.x, b.x, -a.y * b.y), fmaf(a.x, b.y, a.y * b.x));
}
__device__ __forceinline__ float2 cfma(float2 a, float2 b, float2 c) {
    c.x = fmaf(a.x, b.x, fmaf(-a.y, b.y, c.x));
    c.y = fmaf(a.x, b.y, fmaf(a.y, b.x, c.y));
    return c;
}
__device__ __forceinline__ float2 cmulc(float2 a, float2 b) {  // a*conj(b)
    return make_float2(fmaf(a.x, b.x, a.y * b.y), fmaf(a.y, b.x, -a.x * b.y));
}

// Sub-env for one j value: u64s packed along r1 (bra low bit); fields per r0.
struct Sub { u64 R0, I0, R1, I1; };

__device__ __forceinline__ void pket_in(Sub& E,
        u64 w0x, u64 w0y, u64 w0yn, u64 w1x, u64 w1y, u64 w1yn) {
    u64 nR0 = ffma2(E.I1, w1yn, ffma2(E.R1, w1x, ffma2(E.I0, w0yn, fmul2(E.R0, w0x))));
    u64 nI0 = ffma2(E.R1, w1y,  ffma2(E.I1, w1x, ffma2(E.R0, w0y,  fmul2(E.I0, w0x))));
    u64 nR1 = ffma2(E.I1, w0yn, ffma2(E.R1, w0x, ffma2(E.I0, w1yn, fmul2(E.R0, w1x))));
    u64 nI1 = ffma2(E.R1, w0y,  ffma2(E.I1, w0x, ffma2(E.R0, w1y,  fmul2(E.I0, w1x))));
    E.R0 = nR0; E.I0 = nI0; E.R1 = nR1; E.I1 = nI1;
}
__device__ __forceinline__ void pbra_in(Sub& E,
        u64 w0x, u64 w0y, u64 w0yn, u64 w1x, u64 w1y, u64 w1yn) {
    u64 sR0 = swp(E.R0), sI0 = swp(E.I0), sR1 = swp(E.R1), sI1 = swp(E.I1);
    u64 nR0 = ffma2(sI0, w1y,  ffma2(sR0, w1x, ffma2(E.I0, w0y,  fmul2(E.R0, w0x))));
    u64 nI0 = ffma2(sR0, w1yn, ffma2(sI0, w1x, ffma2(E.R0, w0yn, fmul2(E.I0, w0x))));
    u64 nR1 = ffma2(sI1, w1y,  ffma2(sR1, w1x, ffma2(E.I1, w0y,  fmul2(E.R1, w0x))));
    u64 nI1 = ffma2(sR1, w1yn, ffma2(sI1, w1x, ffma2(E.R1, w0yn, fmul2(E.I1, w0x))));
    E.R0 = nR0; E.I0 = nI0; E.R1 = nR1; E.I1 = nI1;
}
// lane ket pass; gates per r0: (a0*,b0*) for r0=0, (a1*,b1*) for r0=1 (splatted)
__device__ __forceinline__ void pket_lane(Sub& E, int m,
        u64 a0x, u64 a0y, u64 a0yn, u64 b0x, u64 b0y, u64 b0yn,
        u64 a1x, u64 a1y, u64 a1yn, u64 b1x, u64 b1y, u64 b1yn) {
    u64 Rp0 = shfl64(E.R0, m), Ip0 = shfl64(E.I0, m);
    u64 Rp1 = shfl64(E.R1, m), Ip1 = shfl64(E.I1, m);
    u64 nR0 = ffma2(Ip0, b0yn, ffma2(Rp0, b0x, ffma2(E.I0, a0yn, fmul2(E.R0, a0x))));
    u64 nI0 = ffma2(Rp0, b0y,  ffma2(Ip0, b0x, ffma2(E.R0, a0y,  fmul2(E.I0, a0x))));
    u64 nR1 = ffma2(Ip1, b1yn, ffma2(Rp1, b1x, ffma2(E.I1, a1yn, fmul2(E.R1, a1x))));
    u64 nI1 = ffma2(Rp1, b1y,  ffma2(Ip1, b1x, ffma2(E.R1, a1y,  fmul2(E.I1, a1x))));
    E.R0 = nR0; E.I0 = nI0; E.R1 = nR1; E.I1 = nI1;
}
// lane bra pass, conj; packed gates per r1 slot: AX={a_lo.x,a_hi.x} etc.
__device__ __forceinline__ void pbra_lane(Sub& E, int m,
        u64 AX, u64 AY, u64 AYn, u64 BX, u64 BY, u64 BYn) {
    u64 Rp0 = shfl64(E.R0, m), Ip0 = shfl64(E.I0, m);
    u64 Rp1 = shfl64(E.R1, m), Ip1 = shfl64(E.I1, m);
    u64 nR0 = ffma2(Ip0, BY,  ffma2(Rp0, BX, ffma2(E.I0, AY,  fmul2(E.R0, AX))));
    u64 nI0 = ffma2(Rp0, BYn, ffma2(Ip0, BX, ffma2(E.R0, AYn, fmul2(E.I0, AX))));
    u64 nR1 = ffma2(Ip1, BY,  ffma2(Rp1, BX, ffma2(E.I1, AY,  fmul2(E.R1, AX))));
    u64 nI1 = ffma2(Rp1, BYn, ffma2(Ip1, BX, ffma2(E.R1, AYn, fmul2(E.I1, AX))));
    E.R0 = nR0; E.I0 = nI0; E.R1 = nR1; E.I1 = nI1;
}
// in-thread j pass: out[0]=G0*in[0]+G1*in[1], out[1]=G0*in[1]+G1*in[0]
__device__ __forceinline__ void jpass(Sub& A, Sub& B,
        u64 G0x, u64 G0y, u64 G0yn, u64 G1x, u64 G1y, u64 G1yn) {
    u64 nAR0 = ffma2(G1yn, B.I0, ffma2(G1x, B.R0, ffma2(G0yn, A.I0, fmul2(G0x, A.R0))));
    u64 nAI0 = ffma2(G1y,  B.R0, ffma2(G1x, B.I0, ffma2(G0y,  A.R0, fmul2(G0x, A.I0))));
    u64 nAR1 = ffma2(G1yn, B.I1, ffma2(G1x, B.R1, ffma2(G0yn, A.I1, fmul2(G0x, A.R1))));
    u64 nAI1 = ffma2(G1y,  B.R1, ffma2(G1x, B.I1, ffma2(G0y,  A.R1, fmul2(G0x, A.I1))));
    u64 nBR0 = ffma2(G1yn, A.I0, ffma2(G1x, A.R0, ffma2(G0yn, B.I0, fmul2(G0x, B.R0))));
    u64 nBI0 = ffma2(G1y,  A.R0, ffma2(G1x, A.I0, ffma2(G0y,  B.R0, fmul2(G0x, B.I0))));
    u64 nBR1 = ffma2(G1yn, A.I1, ffma2(G1x, A.R1, ffma2(G0yn, B.I1, fmul2(G0x, B.R1))));
    u64 nBI1 = ffma2(G1y,  A.R1, ffma2(G1x, A.I1, ffma2(G0y,  B.R1, fmul2(G0x, B.I1))));
    A.R0 = nAR0; A.I0 = nAI0; A.R1 = nAR1; A.I1 = nAI1;
    B.R0 = nBR0; B.I0 = nBI0; B.R1 = nBR1; B.I1 = nBI1;
}

__global__ __launch_bounds__(64) void pqc_mps_kernel(
    const float* __restrict__ ctx,   // [B, 256]
    const float* __restrict__ Wm,    // [16, 256]
    const float* __restrict__ bv,    // [16]
    const float* __restrict__ prm,   // [4, 16, 3]
    float* __restrict__ out,         // [B, 16]
    int B)
{
    // Hist slots 0..6 = L_1..L_7, 7..14 = R_8..R_15; [slot][k=0..7][lane]
    __shared__ u64   Hist[15][8][32];
    __shared__ float2 Usm[4][16][4];
    __shared__ float2 wsm[2][16][2];
    __shared__ float  pf[2][16];

    const int tid  = threadIdx.x;
    const int lane = tid & 31;
    const int warp = tid >> 5;      // 0 = L chains, 1 = R chains
    const int hf   = (lane >> 4) & 1;   // batch within CTA
    const int bat  = blockIdx.x * 2 + hf;

    // ---------- fused variational gates (batch independent) ----------
    {
        int l = tid >> 4, q = tid & 15;
        const float* p = prm + (size_t)(l * 16 + q) * 3;
        float ca = cosf(0.5f * p[0]), sa = sinf(0.5f * p[0]);
        float cb = cosf(0.5f * p[1]), sb = sinf(0.5f * p[1]);
        float cg = cosf(0.5f * p[2]), sg = sinf(0.5f * p[2]);
        float2 X00 = make_float2(ca, 0.f), X01 = make_float2(0.f, -sa);
        float2 M00 = make_float2(cb * X00.x - sb * X01.x, cb * X00.y - sb * X01.y);
        float2 M01 = make_float2(cb * X01.x - sb * X00.x, cb * X01.y - sb * X00.y);
        float2 M10 = make_float2(sb * X00.x + cb * X01.x, sb * X00.y + cb * X01.y);
        float2 M11 = make_float2(sb * X01.x + cb * X00.x, sb * X01.y + cb * X00.y);
        float2 em = make_float2(cg, -sg), ep = make_float2(cg, sg);
        Usm[l][q][0] = cmul(em, M00);
        Usm[l][q][1] = cmul(em, M01);
        Usm[l][q][2] = cmul(ep, M10);
        Usm[l][q][3] = cmul(ep, M11);
    }
    // ---------- encoding dots: warp b handles batch b; 16 q x 2 halves ----------
    {
        int b = warp, q = lane >> 1, hh = lane & 1;
        int eb = blockIdx.x * 2 + b;
        float acc = 0.f;
        if (eb < B) {
            const float4* cr = (const float4*)(ctx + (size_t)eb * 256) + hh * 32;
            const float4* wr = (const float4*)(Wm + (size_t)q * 256) + hh * 32;
            #pragma unroll
            for (int k = 0; k < 32; ++k) {
                float4 c = cr[k], w = wr[k];
                acc = fmaf(c.x, w.x, acc); acc = fmaf(c.y, w.y, acc);
                acc = fmaf(c.z, w.z, acc); acc = fmaf(c.w, w.w, acc);
            }
        }
        acc += __shfl_xor_sync(0xffffffffu, acc, 1);
        if (hh == 0) pf[b][q] = acc;
    }
    __syncthreads();
    if (tid < 32) {
        int b = tid >> 4, q = tid & 15;
        float ang = 3.14159265358979323846f * tanhf(pf[b][q] + bv[q]);
        float h = 0.5f * ang;
        float2 v0 = make_float2(cosf(h), 0.f);
        float2 v1 = make_float2(0.f, -sinf(h));
        wsm[b][q][0] = cfma(Usm[0][q][1], v1, cmul(Usm[0][q][0], v0));
        wsm[b][q][1] = cfma(Usm[0][q][3], v1, cmul(Usm[0][q][2], v0));
    }
    __syncthreads();

    const int l0 = lane & 1, l1 = (lane >> 1) & 1;
    const int l2 = (lane >> 2) & 1, l3 = (lane >> 3) & 1;

    Sub S0, S1;   // j = 0 / 1
    if (warp == 0) {
        S0.R0 = pk2((lane & 15) == 0 ? 1.f : 0.f, 0.f);
        S0.I0 = 0; S0.R1 = 0; S0.I1 = 0;
        S1.R0 = 0; S1.I0 = 0; S1.R1 = 0; S1.I1 = 0;
    } else {
        S0.R0 = pk2(1.f, 1.f); S0.R1 = pk2(1.f, 1.f); S0.I0 = 0; S0.I1 = 0;
        S1 = S0;
    }

    #pragma unroll 1
    for (int i = 0; i < 16; ++i) {
        if (warp == 0) {
            // ---- Z_{i-1} from E (=L_i) and Hist[i-1] (=R_i), i >= 8 ----
            if (i >= 8) {
                const u64* H = &Hist[i - 1][0][lane];
                u64 P0 = ffma2(S0.R1, H[64],  fmul2(S0.R0, H[0]));
                u64 N0 = ffma2(S0.I1, H[96],  fmul2(S0.I0, H[32]));
                u64 P1 = ffma2(S1.R1, H[192], fmul2(S1.R0, H[128]));
                u64 N1 = ffma2(S1.I1, H[224], fmul2(S1.I0, H[160]));
                float2 p0 = up2(P0), n0 = up2(N0), p1 = up2(P1), n1 = up2(N1);
                float z = (p0.x + p0.y - n0.x - n0.y) - (p1.x + p1.y - n1.x - n1.y);
                z += __shfl_xor_sync(0xffffffffu, z, 1);
                z += __shfl_xor_sync(0xffffffffu, z, 2);
                z += __shfl_xor_sync(0xffffffffu, z, 4);
                z += __shfl_xor_sync(0xffffffffu, z, 8);
                if ((lane & 15) == 0 && bat < B) out[(size_t)bat * 16 + (i - 1)] = z;
            }
            // ---- transfer site q = i (left order) ----
            const int q = i;
            float2 w0 = wsm[hf][q][0], w1 = wsm[hf][q][1];
            u64 w0x = spl(w0.x), w0y = spl(w0.y), w0yn = spl(-w0.y);
            u64 w1x = spl(w1.x), w1y = spl(w1.y), w1yn = spl(-w1.y);
            pket_in(S0, w0x, w0y, w0yn, w1x, w1y, w1yn);
            pket_in(S1, w0x, w0y, w0yn, w1x, w1y, w1yn);
            pbra_in(S0, w0x, w0y, w0yn, w1x, w1y, w1yn);
            pbra_in(S1, w0x, w0y, w0yn, w1x, w1y, w1yn);
            float2 u20 = Usm[1][q][0], u21 = Usm[1][q][1];
            float2 u22 = Usm[1][q][2], u23 = Usm[1][q][3];
            {
                u64 a0x = spl(u20.x), a0y = spl(u20.y), a0yn = spl(-u20.y);
                u64 b0x = spl(u22.x), b0y = spl(u22.y), b0yn = spl(-u22.y);
                u64 a1x = spl(u21.x), a1y = spl(u21.y), a1yn = spl(-u21.y);
                u64 b1x = spl(u23.x), b1y = spl(u23.y), b1yn = spl(-u23.y);
                pket_lane(S0, 1, a0x,a0y,a0yn,b0x,b0y,b0yn, a1x,a1y,a1yn,b1x,b1y,b1yn);
                pket_lane(S1, 1, a0x,a0y,a0yn,b0x,b0y,b0yn, a1x,a1y,a1yn,b1x,b1y,b1yn);
            }
            {
                u64 AX = pk2(u20.x, u21.x), AY = pk2(u20.y, u21.y), AYn = pk2(-u20.y, -u21.y);
                u64 BX = pk2(u22.x, u23.x), BY = pk2(u22.y, u23.y), BYn = pk2(-u22.y, -u23.y);
                pbra_lane(S0, 2, AX, AY, AYn, BX, BY, BYn);
                pbra_lane(S1, 2, AX, AY, AYn, BX, BY, BYn);
            }
            {
                float2 g0 = Usm[2][q][l0], g1 = Usm[2][q][2 | l0];
                u64 gx = spl(g0.x), gy = spl(g0.y), gyn = spl(-g0.y);
                u64 hx = spl(g1.x), hy = spl(g1.y), hyn = spl(-g1.y);
                pket_lane(S0, 4, gx,gy,gyn,hx,hy,hyn, gx,gy,gyn,hx,hy,hyn);
                pket_lane(S1, 4, gx,gy,gyn,hx,hy,hyn, gx,gy,gyn,hx,hy,hyn);
            }
            {
                float2 h0 = Usm[2][q][l1], h1 = Usm[2][q][2 | l1];
                u64 AX = spl(h0.x), AY = spl(h0.y), AYn = spl(-h0.y);
                u64 BX = spl(h1.x), BY = spl(h1.y), BYn = spl(-h1.y);
                pbra_lane(S0, 8, AX, AY, AYn, BX, BY, BYn);
                pbra_lane(S1, 8, AX, AY, AYn, BX, BY, BYn);
            }
            {
                float2 G0 = cmulc(Usm[3][q][l2], Usm[3][q][l3]);
                float2 G1 = cmulc(Usm[3][q][2 | l2], Usm[3][q][2 | l3]);
                jpass(S0, S1, spl(G0.x), spl(G0.y), spl(-G0.y),
                              spl(G1.x), spl(G1.y), spl(-G1.y));
            }
            if (i <= 6) {
                u64* H = &Hist[i][0][lane];
                H[0]   = S0.R0; H[32]  = S0.I0; H[64]  = S0.R1; H[96]  = S0.I1;
                H[128] = S1.R0; H[160] = S1.I0; H[192] = S1.R1; H[224] = S1.I1;
            }
        } else if (i < 15) {
            // ---- transfer site q = 15 - i (right order) ----
            const int q = 15 - i;
            {
                float2 G0 = cmulc(Usm[3][q][l2], Usm[3][q][l3]);
                float2 G1 = cmulc(Usm[3][q][2 | l2], Usm[3][q][2 | l3]);
                jpass(S0, S1, spl(G0.x), spl(G0.y), spl(-G0.y),
                              spl(G1.x), spl(G1.y), spl(-G1.y));
            }
            {
                float2 g0 = Usm[2][q][l0], g1 = Usm[2][q][2 | l0];
                u64 gx = spl(g0.x), gy = spl(g0.y), gyn = spl(-g0.y);
                u64 hx = spl(g1.x), hy = spl(g1.y), hyn = spl(-g1.y);
                pket_lane(S0, 4, gx,gy,gyn,hx,hy,hyn, gx,gy,gyn,hx,hy,hyn);
                pket_lane(S1, 4, gx,gy,gyn,hx,hy,hyn, gx,gy,gyn,hx,hy,hyn);
            }
            {
                float2 h0 = Usm[2][q][l1], h1 = Usm[2][q][2 | l1];
                u64 AX = spl(h0.x), AY = spl(h0.y), AYn = spl(-h0.y);
                u64 BX = spl(h1.x), BY = spl(h1.y), BYn = spl(-h1.y);
                pbra_lane(S0, 8, AX, AY, AYn, BX, BY, BYn);
                pbra_lane(S1, 8, AX, AY, AYn, BX, BY, BYn);
            }
            float2 u20 = Usm[1][q][0], u21 = Usm[1][q][1];
            float2 u22 = Usm[1][q][2], u23 = Usm[1][q][3];
            {
                u64 a0x = spl(u20.x), a0y = spl(u20.y), a0yn = spl(-u20.y);
                u64 b0x = spl(u22.x), b0y = spl(u22.y), b0yn = spl(-u22.y);
                u64 a1x = spl(u21.x), a1y = spl(u21.y), a1yn = spl(-u21.y);
                u64 b1x = spl(u23.x), b1y = spl(u23.y), b1yn = spl(-u23.y);
                pket_lane(S0, 1, a0x,a0y,a0yn,b0x,b0y,b0yn, a1x,a1y,a1yn,b1x,b1y,b1yn);
                pket_lane(S1, 1, a0x,a0y,a0yn,b0x,b0y,b0yn, a1x,a1y,a1yn,b1x,b1y,b1yn);
            }
            {
                u64 AX = pk2(u20.x, u21.x), AY = pk2(u20.y, u21.y), AYn = pk2(-u20.y, -u21.y);
                u64 BX = pk2(u22.x, u23.x), BY = pk2(u22.y, u23.y), BYn = pk2(-u22.y, -u23.y);
                pbra_lane(S0, 2, AX, AY, AYn, BX, BY, BYn);
                pbra_lane(S1, 2, AX, AY, AYn, BX, BY, BYn);
            }
            float2 w0 = wsm[hf][q][0], w1 = wsm[hf][q][1];
            u64 w0x = spl(w0.x), w0y = spl(w0.y), w0yn = spl(-w0.y);
            u64 w1x = spl(w1.x), w1y = spl(w1.y), w1yn = spl(-w1.y);
            pket_in(S0, w0x, w0y, w0yn, w1x, w1y, w1yn);
            pket_in(S1, w0x, w0y, w0yn, w1x, w1y, w1yn);
            pbra_in(S0, w0x, w0y, w0yn, w1x, w1y, w1yn);
            pbra_in(S1, w0x, w0y, w0yn, w1x, w1y, w1yn);
            if (i <= 7) {
                u64* H = &Hist[14 - i][0][lane];
                H[0]   = S0.R0; H[32]  = S0.I0; H[64]  = S0.R1; H[96]  = S0.I1;
                H[128] = S1.R0; H[160] = S1.I0; H[192] = S1.R1; H[224] = S1.I1;
            }
            if (i >= 8) {
                // ---- Z_{14-i} from E (=R_{15-i}) and Hist[14-i] (=L_{15-i}) ----
                const u64* H = &Hist[14 - i][0][lane];
                u64 P0 = ffma2(S0.R1, H[64],  fmul2(S0.R0, H[0]));
                u64 N0 = ffma2(S0.I1, H[96],  fmul2(S0.I0, H[32]));
                u64 P1 = ffma2(S1.R1, H[192], fmul2(S1.R0, H[128]));
                u64 N1 = ffma2(S1.I1, H[224], fmul2(S1.I0, H[160]));
                float2 p0 = up2(P0), n0 = up2(N0), p1 = up2(P1), n1 = up2(N1);
                float z = (p0.x + p0.y - n0.x - n0.y) - (p1.x + p1.y - n1.x - n1.y);
                z += __shfl_xor_sync(0xffffffffu, z, 1);
                z += __shfl_xor_sync(0xffffffffu, z, 2);
                z += __shfl_xor_sync(0xffffffffu, z, 4);
                z += __shfl_xor_sync(0xffffffffu, z, 8);
                if ((lane & 15) == 0 && bat < B) out[(size_t)bat * 16 + (14 - i)] = z;
            }
        }
        __syncthreads();
    }

    // ---- epilogue: Z_15 from L_16 and R_16 = all-ones ----
    if (warp == 0) {
        float2 a0 = up2(S0.R0), a1 = up2(S0.R1);
        float2 b0 = up2(S1.R0), b1 = up2(S1.R1);
        float z = (a0.x + a0.y + a1.x + a1.y) - (b0.x + b0.y + b1.x + b1.y);
        z += __shfl_xor_sync(0xffffffffu, z, 1);
        z += __shfl_xor_sync(0xffffffffu, z, 2);
        z += __shfl_xor_sync(0xffffffffu, z, 4);
        z += __shfl_xor_sync(0xffffffffu, z, 8);
        if ((lane & 15) == 0 && bat < B) out[(size_t)bat * 16 + 15] = z;
    }
}

extern "C" void kernel_launch(void* const* d_in, const int* in_sizes, int n_in,
                              void* d_out, int out_size) {
    const float* ctx = nullptr;
    const float* Wm  = nullptr;
    const float* bv  = nullptr;
    const float* prm = nullptr;
    for (int i = 0; i < n_in; ++i) {
        int sz = in_sizes[i];
        const float* p = (const float*)d_in[i];
        if (sz == 16)        bv  = p;
        else if (sz == 192)  prm = p;
        else if (sz == 4096) Wm  = p;
        else                 ctx = p;  // B*256
    }
    if (!ctx) ctx = (const float*)d_in[0];
    if (!Wm)  Wm  = (const float*)d_in[1];
    if (!bv)  bv  = (const float*)d_in[2];
    if (!prm) prm = (const float*)d_in[3];

    float* out = (float*)d_out;
    int B = out_size / 16;
    if (B <= 0) return;
    int blocks = (B + 1) / 2;
    pqc_mps_kernel<<<blocks, 64>>>(ctx, Wm, bv, prm, out, B);
}